// round 6
// baseline (speedup 1.0000x reference)
#include <cuda_runtime.h>
#include <cuda_bf16.h>
#include <math.h>
#include <stdint.h>

// Problem shape
#define BB 8
#define TT 2048
#define CC 1024
#define HH 16
#define DD 64
#define MTOT (BB*TT)      // 16384
#define KDIM 1024
#define N_QKV 3072
#define N_PROJ 1024

// ---------------- scratch (__device__ globals; no allocation allowed) -------
__device__ float         g_qkv [(size_t)MTOT * N_QKV];   // phi_q | phi_k*m | v*m
__device__ __nv_bfloat16 g_xhi [(size_t)MTOT * KDIM];
__device__ __nv_bfloat16 g_xlo [(size_t)MTOT * KDIM];
__device__ __nv_bfloat16 g_wahi[(size_t)N_QKV * KDIM];   // transposed [N,K]
__device__ __nv_bfloat16 g_walo[(size_t)N_QKV * KDIM];
__device__ __nv_bfloat16 g_wphi[(size_t)N_PROJ * KDIM];
__device__ __nv_bfloat16 g_wplo[(size_t)N_PROJ * KDIM];
__device__ __nv_bfloat16 g_yhi [(size_t)MTOT * CC];
__device__ __nv_bfloat16 g_ylo [(size_t)MTOT * CC];
__device__ float g_kvp[8 * BB*HH * DD*DD];
__device__ float g_ksp[8 * BB*HH * DD];
__device__ float g_kv [BB*HH * DD*DD];
__device__ float g_ks [BB*HH * DD];

// ---------------- helpers ----------------------------------------------------
__device__ __forceinline__ uint32_t smem_u32(const void* p) {
    uint32_t a;
    asm("{ .reg .u64 t; cvta.to.shared.u64 t, %1; cvt.u32.u64 %0, t; }"
        : "=r"(a) : "l"(p));
    return a;
}
__device__ __forceinline__ void cpasync16(uint32_t dst, const void* src) {
    asm volatile("cp.async.cg.shared.global [%0], [%1], 16;" :: "r"(dst), "l"(src));
}
#define CP_COMMIT() asm volatile("cp.async.commit_group;" ::: "memory")
#define CP_WAIT1()  asm volatile("cp.async.wait_group 1;" ::: "memory")

__device__ __forceinline__ void ldsm4(uint32_t (&r)[4], uint32_t addr) {
    asm volatile("ldmatrix.sync.aligned.m8n8.x4.shared.b16 {%0,%1,%2,%3}, [%4];"
                 : "=r"(r[0]), "=r"(r[1]), "=r"(r[2]), "=r"(r[3]) : "r"(addr));
}
__device__ __forceinline__ void mma16816(float (&c)[4], const uint32_t (&a)[4],
                                         uint32_t b0, uint32_t b1) {
    asm volatile(
        "mma.sync.aligned.m16n8k16.row.col.f32.bf16.bf16.f32 "
        "{%0,%1,%2,%3}, {%4,%5,%6,%7}, {%8,%9}, {%0,%1,%2,%3};"
        : "+f"(c[0]), "+f"(c[1]), "+f"(c[2]), "+f"(c[3])
        : "r"(a[0]), "r"(a[1]), "r"(a[2]), "r"(a[3]), "r"(b0), "r"(b1));
}

__device__ __forceinline__ void split2(float v, __nv_bfloat16& h, __nv_bfloat16& l) {
    h = __float2bfloat16(v);
    l = __float2bfloat16(v - __bfloat162float(h));
}

// FFMA-only exp(x): range-reduce to 2^n * 2^f, Taylor deg-5 for 2^f on
// f in [-0.5, 0.5] (rel err ~2.4e-6). No MUFU — avoids the EX2 throughput
// bottleneck (rt=8 cyc/SMSP) in the GEMM epilogue.
__device__ __forceinline__ float fexp(float x) {
    x = fmaxf(x, -80.f);
    float t = x * 1.4426950408889634f;            // x * log2(e)
    float r = t + 12582912.0f;                    // round-to-nearest
    int   n = __float_as_int(r) - 0x4B400000;     // integer part
    float f = t - (r - 12582912.0f);              // frac in [-0.5, 0.5]
    float g = f * 0.6931471805599453f;            // f * ln2
    float p = fmaf(g, 0.008333333f, 0.041666667f);
    p = fmaf(g, p, 0.166666667f);
    p = fmaf(g, p, 0.5f);
    p = fmaf(g, p, 1.0f);
    p = fmaf(g, p, 1.0f);
    return __int_as_float(__float_as_int(p) + (n << 23));
}

// XOR-swizzled smem offset: 64B rows of 4x16B chunks; chunk ^= (row>>1)&3.
__device__ __forceinline__ uint32_t swz(int row, int ch) {
    return (uint32_t)((row << 6) + (((ch ^ (row >> 1)) & 3) << 4));
}

// ---------------- conversion kernels ----------------------------------------
__global__ __launch_bounds__(256)
void split_x_kernel(const float4* __restrict__ in, uint2* __restrict__ hi,
                    uint2* __restrict__ lo) {
    size_t i = (size_t)blockIdx.x * blockDim.x + threadIdx.x;
    float4 v = in[i];
    __nv_bfloat16 h0, h1, h2, h3, l0, l1, l2, l3;
    split2(v.x, h0, l0); split2(v.y, h1, l1);
    split2(v.z, h2, l2); split2(v.w, h3, l3);
    uint32_t ha = (uint32_t)__bfloat16_as_ushort(h0) | ((uint32_t)__bfloat16_as_ushort(h1) << 16);
    uint32_t hb = (uint32_t)__bfloat16_as_ushort(h2) | ((uint32_t)__bfloat16_as_ushort(h3) << 16);
    uint32_t la = (uint32_t)__bfloat16_as_ushort(l0) | ((uint32_t)__bfloat16_as_ushort(l1) << 16);
    uint32_t lb = (uint32_t)__bfloat16_as_ushort(l2) | ((uint32_t)__bfloat16_as_ushort(l3) << 16);
    hi[i] = make_uint2(ha, hb);
    lo[i] = make_uint2(la, lb);
}

// w [K,N] row-major -> hi/lo [N,K] (K-major), split to bf16
__global__ __launch_bounds__(256)
void transpose_split_kernel(const float* __restrict__ w, __nv_bfloat16* __restrict__ hi,
                            __nv_bfloat16* __restrict__ lo, int K, int N) {
    __shared__ float t[32][33];
    int n0 = blockIdx.x * 32, k0 = blockIdx.y * 32;
    int tx = threadIdx.x, ty = threadIdx.y;
#pragma unroll
    for (int i = 0; i < 4; i++)
        t[ty + i * 8][tx] = w[(size_t)(k0 + ty + i * 8) * N + n0 + tx];
    __syncthreads();
#pragma unroll
    for (int i = 0; i < 4; i++) {
        float v = t[tx][ty + i * 8];
        __nv_bfloat16 h, l;
        split2(v, h, l);
        size_t o = (size_t)(n0 + ty + i * 8) * K + k0 + tx;
        hi[o] = h; lo[o] = l;
    }
}

// ---------------- mma.sync split-bf16 GEMM ----------------------------------
// C[M,N] (fp32) = A[M,K] * B[N,K]^T + bias. A/B as bf16 hi+lo (3-term emulation).
// Block: 128x128, BK=32, XOR-swizzled smem (32KB/stage), 3 buffers / depth-2
// prefetch, 8 warps (2x4), warp tile 64x32, 2 CTAs/SM.
#define BKG 32
#define OPB (128 * 64)          // 8192 B per operand tile
#define STGB (4 * OPB)          // 32768 B per stage
#define NSTG 3
#define GSMEM (NSTG * STGB)     // 98304 B

template<int EPI>
__global__ __launch_bounds__(256, 2)
void mgemm(const __nv_bfloat16* __restrict__ Ahi, const __nv_bfloat16* __restrict__ Alo,
           const __nv_bfloat16* __restrict__ Bhi, const __nv_bfloat16* __restrict__ Blo,
           const float* __restrict__ bias, const int* __restrict__ am,
           float* __restrict__ Cout, int N)
{
    extern __shared__ char smem_raw[];
    const uint32_t sbase = smem_u32(smem_raw);
    const int tid = threadIdx.x;
    const int wid = tid >> 5, lane = tid & 31;
    const int warp_row = wid & 1;        // 0..1  (64 rows each)
    const int warp_col = wid >> 1;       // 0..3  (32 cols each)
    const int bm = blockIdx.y * 128;
    const int bn = blockIdx.x * 128;

    float acc[4][4][4];                  // [m-tile][n-tile][frag]
#pragma unroll
    for (int i = 0; i < 4; i++)
#pragma unroll
        for (int j = 0; j < 4; j++)
#pragma unroll
            for (int q = 0; q < 4; q++) acc[i][j][q] = 0.f;

    // stage loader: 128 rows x 4 chunks(16B) per operand; 2 rows/thread
    auto load_stage = [&](int s) {
        const int k0 = s * BKG;
        const uint32_t sb = sbase + (s % NSTG) * STGB;
#pragma unroll
        for (int i = 0; i < 2; i++) {
            int c = tid + i * 256;
            int row = c >> 2, ch = c & 3;
            uint32_t so = swz(row, ch);
            size_t ga = (size_t)(bm + row) * KDIM + k0 + ch * 8;
            size_t gb = (size_t)(bn + row) * KDIM + k0 + ch * 8;
            cpasync16(sb + 0 * OPB + so, Ahi + ga);
            cpasync16(sb + 1 * OPB + so, Alo + ga);
            cpasync16(sb + 2 * OPB + so, Bhi + gb);
            cpasync16(sb + 3 * OPB + so, Blo + gb);
        }
        CP_COMMIT();
    };

    const int NS = KDIM / BKG;   // 32
    load_stage(0); load_stage(1);

    // per-lane ldmatrix fragment coordinates
    const int a_r = (lane & 7) + 8 * ((lane >> 3) & 1);   // row offset within 16
    const int a_k = 8 * (lane >> 4);                      // k offset 0/8
    const int b_r = (lane & 7) + 8 * (lane >> 4);         // n offset within 16
    const int b_k = 8 * ((lane >> 3) & 1);                // k offset 0/8

    for (int s = 0; s < NS; s++) {
        CP_WAIT1();
        __syncthreads();
        if (s + 2 < NS) load_stage(s + 2);

        const uint32_t sb = sbase + (s % NSTG) * STGB;

#pragma unroll
        for (int kk = 0; kk < 2; kk++) {
            uint32_t ah[4][4], al[4][4];
#pragma unroll
            for (int mi = 0; mi < 4; mi++) {
                int r = warp_row * 64 + mi * 16 + a_r;
                int ch = (kk * 16 + a_k) >> 3;
                uint32_t ro = swz(r, ch);
                ldsm4(ah[mi], sb + 0 * OPB + ro);
                ldsm4(al[mi], sb + 1 * OPB + ro);
            }
#pragma unroll
            for (int p = 0; p < 2; p++) {
                int rn = warp_col * 32 + p * 16 + b_r;
                int chb = (kk * 16 + b_k) >> 3;
                uint32_t bo = swz(rn, chb);
                uint32_t bh[4], bl[4];
                ldsm4(bh, sb + 2 * OPB + bo);
                ldsm4(bl, sb + 3 * OPB + bo);
                // term-major: 8 independent MMAs per term -> no back-to-back
                // accumulator dependency chains
#pragma unroll
                for (int mi = 0; mi < 4; mi++)
#pragma unroll
                    for (int j = 0; j < 2; j++)
                        mma16816(acc[mi][2 * p + j], ah[mi], bh[2 * j], bh[2 * j + 1]);
#pragma unroll
                for (int mi = 0; mi < 4; mi++)
#pragma unroll
                    for (int j = 0; j < 2; j++)
                        mma16816(acc[mi][2 * p + j], ah[mi], bl[2 * j], bl[2 * j + 1]);
#pragma unroll
                for (int mi = 0; mi < 4; mi++)
#pragma unroll
                    for (int j = 0; j < 2; j++)
                        mma16816(acc[mi][2 * p + j], al[mi], bh[2 * j], bh[2 * j + 1]);
            }
        }
    }

    // ---------------- epilogue ----------------
    const int er = lane >> 2;            // 0..7
    const int ec = (lane & 3) * 2;       // 0,2,4,6
#pragma unroll
    for (int mi = 0; mi < 4; mi++) {
#pragma unroll
        for (int half = 0; half < 2; half++) {
            int row = bm + warp_row * 64 + mi * 16 + er + half * 8;
            float mv = 1.f;
            if (EPI == 0) mv = (am[row] > 0) ? 1.f : 0.f;
#pragma unroll
            for (int ni = 0; ni < 4; ni++) {
                int col = bn + warp_col * 32 + ni * 8 + ec;
                float v0 = acc[mi][ni][2 * half]     + bias[col];
                float v1 = acc[mi][ni][2 * half + 1] + bias[col + 1];
                if (EPI == 0) {
                    if (col < 2048) {
                        v0 = (v0 > 0.f) ? (v0 + 1.f) : fexp(v0);   // elu + 1
                        v1 = (v1 > 0.f) ? (v1 + 1.f) : fexp(v1);
                    }
                    if (col >= 1024) { v0 *= mv; v1 *= mv; }
                }
                *(float2*)(Cout + (size_t)row * N + col) = make_float2(v0, v1);
            }
        }
    }
}

// ---------------- K2: per (b,h,chunk) partial kv / ksum ---------------------
__global__ __launch_bounds__(256)
void kv_partial(const float* __restrict__ qkv, float* __restrict__ kvp,
                float* __restrict__ ksp)
{
    __shared__ float ks[16][64];
    __shared__ float vs[16][64];

    const int bh = blockIdx.x >> 3;
    const int chn = blockIdx.x & 7;
    const int b = bh >> 4, h = bh & 15;
    const int tid = threadIdx.x;

    const float* kb = qkv + (size_t)b * TT * N_QKV + 1024 + h * DD;
    const float* vb = kb + 1024;

    const int lr  = tid >> 4;
    const int lc4 = (tid & 15) * 4;
    const int i0  = (tid >> 4) * 4;
    const int j0  = (tid & 15) * 4;

    float acc[4][4];
#pragma unroll
    for (int i = 0; i < 4; i++)
#pragma unroll
        for (int j = 0; j < 4; j++) acc[i][j] = 0.f;
    float ksum4[4] = {0.f, 0.f, 0.f, 0.f};
    const bool owns_ksum = ((tid & 15) == 0);

    const int tbeg = chn * (TT / 8);
    for (int t0 = tbeg; t0 < tbeg + TT / 8; t0 += 16) {
        size_t off = (size_t)(t0 + lr) * N_QKV + lc4;
        *(float4*)&ks[lr][lc4] = *(const float4*)(kb + off);
        *(float4*)&vs[lr][lc4] = *(const float4*)(vb + off);
        __syncthreads();
#pragma unroll
        for (int t = 0; t < 16; t++) {
            float4 k4 = *(float4*)&ks[t][i0];
            float4 v4 = *(float4*)&vs[t][j0];
            float ka[4] = {k4.x, k4.y, k4.z, k4.w};
            float va[4] = {v4.x, v4.y, v4.z, v4.w};
#pragma unroll
            for (int i = 0; i < 4; i++)
#pragma unroll
                for (int j = 0; j < 4; j++)
                    acc[i][j] = fmaf(ka[i], va[j], acc[i][j]);
            if (owns_ksum) {
#pragma unroll
                for (int i = 0; i < 4; i++) ksum4[i] += ka[i];
            }
        }
        __syncthreads();
    }

    float* kvdst = kvp + ((size_t)chn * 128 + bh) * DD * DD;
#pragma unroll
    for (int i = 0; i < 4; i++)
        *(float4*)&kvdst[(i0 + i) * DD + j0] =
            make_float4(acc[i][0], acc[i][1], acc[i][2], acc[i][3]);
    if (owns_ksum) {
#pragma unroll
        for (int i = 0; i < 4; i++)
            ksp[((size_t)chn * 128 + bh) * DD + i0 + i] = ksum4[i];
    }
}

__global__ __launch_bounds__(256)
void kv_reduce(const float* __restrict__ kvp, const float* __restrict__ ksp,
               float* __restrict__ kv, float* __restrict__ ks)
{
    const int bh = blockIdx.x;
    const int tid = threadIdx.x;
    for (int i = tid; i < DD * DD; i += 256) {
        float s = 0.f;
#pragma unroll
        for (int c = 0; c < 8; c++) s += kvp[((size_t)c * 128 + bh) * DD * DD + i];
        kv[(size_t)bh * DD * DD + i] = s;
    }
    if (tid < DD) {
        float s = 0.f;
#pragma unroll
        for (int c = 0; c < 8; c++) s += ksp[((size_t)c * 128 + bh) * DD + tid];
        ks[(size_t)bh * DD + tid] = s;
    }
}

// ---------------- K3: y = (phi_q . kv) / max(phi_q . ksum, eps) -> bf16 hi/lo
__global__ __launch_bounds__(256)
void y_kernel(const float* __restrict__ qkv, const float* __restrict__ kv,
              const float* __restrict__ ksum, __nv_bfloat16* __restrict__ yhi,
              __nv_bfloat16* __restrict__ ylo)
{
    __shared__ float kvs[DD * DD];
    __shared__ float kss[DD];

    const int bh = blockIdx.y;
    const int b = bh >> 4, h = bh & 15;
    const int tid = threadIdx.x;

    const float4* kvsrc = (const float4*)(kv + (size_t)bh * DD * DD);
#pragma unroll
    for (int i = 0; i < 4; i++)
        ((float4*)kvs)[tid + i * 256] = kvsrc[tid + i * 256];
    if (tid < DD) kss[tid] = ksum[bh * DD + tid];
    __syncthreads();

    const int t = blockIdx.x * 128 + (tid >> 1);
    const int f0 = (tid & 1) * 32;
    const float* qrow = qkv + (size_t)(b * TT + t) * N_QKV + h * DD;

    float acc[32];
#pragma unroll
    for (int f = 0; f < 32; f++) acc[f] = 0.f;
    float den = 0.f;

#pragma unroll 4
    for (int d4 = 0; d4 < 16; d4++) {
        float4 q4 = *(const float4*)(qrow + d4 * 4);
        float qa[4] = {q4.x, q4.y, q4.z, q4.w};
#pragma unroll
        for (int u = 0; u < 4; u++) {
            int d = d4 * 4 + u;
            den = fmaf(qa[u], kss[d], den);
            const float* kr = &kvs[d * DD + f0];
#pragma unroll
            for (int f = 0; f < 32; f += 4) {
                float4 kv4 = *(const float4*)(kr + f);
                acc[f]     = fmaf(qa[u], kv4.x, acc[f]);
                acc[f + 1] = fmaf(qa[u], kv4.y, acc[f + 1]);
                acc[f + 2] = fmaf(qa[u], kv4.z, acc[f + 2]);
                acc[f + 3] = fmaf(qa[u], kv4.w, acc[f + 3]);
            }
        }
    }

    const float inv = 1.f / fmaxf(den, 1e-8f);
    const size_t off = (size_t)(b * TT + t) * CC + h * DD + f0;
#pragma unroll
    for (int f = 0; f < 32; f += 8) {
        uint32_t wh[4], wl[4];
#pragma unroll
        for (int j = 0; j < 4; j++) {
            float v0 = acc[f + 2 * j]     * inv;
            float v1 = acc[f + 2 * j + 1] * inv;
            __nv_bfloat16 h0, l0, h1, l1;
            split2(v0, h0, l0);
            split2(v1, h1, l1);
            wh[j] = (uint32_t)__bfloat16_as_ushort(h0) | ((uint32_t)__bfloat16_as_ushort(h1) << 16);
            wl[j] = (uint32_t)__bfloat16_as_ushort(l0) | ((uint32_t)__bfloat16_as_ushort(l1) << 16);
        }
        *(uint4*)(yhi + off + f) = make_uint4(wh[0], wh[1], wh[2], wh[3]);
        *(uint4*)(ylo + off + f) = make_uint4(wl[0], wl[1], wl[2], wl[3]);
    }
}

// ---------------------------------------------------------------------------
extern "C" void kernel_launch(void* const* d_in, const int* in_sizes, int n_in,
                              void* d_out, int out_size)
{
    const float* x      = (const float*)d_in[0];
    const int*   am     = (const int*)  d_in[1];
    const float* w_attn = (const float*)d_in[2];
    const float* b_attn = (const float*)d_in[3];
    const float* w_proj = (const float*)d_in[4];
    const float* b_proj = (const float*)d_in[5];
    float* out = (float*)d_out;

    float *qkv, *kvp, *ksp, *kvb, *ksb;
    __nv_bfloat16 *xhi, *xlo, *wahi, *walo, *wphi, *wplo, *yhi, *ylo;
    cudaGetSymbolAddress((void**)&qkv,  g_qkv);
    cudaGetSymbolAddress((void**)&xhi,  g_xhi);
    cudaGetSymbolAddress((void**)&xlo,  g_xlo);
    cudaGetSymbolAddress((void**)&wahi, g_wahi);
    cudaGetSymbolAddress((void**)&walo, g_walo);
    cudaGetSymbolAddress((void**)&wphi, g_wphi);
    cudaGetSymbolAddress((void**)&wplo, g_wplo);
    cudaGetSymbolAddress((void**)&yhi,  g_yhi);
    cudaGetSymbolAddress((void**)&ylo,  g_ylo);
    cudaGetSymbolAddress((void**)&kvp,  g_kvp);
    cudaGetSymbolAddress((void**)&ksp,  g_ksp);
    cudaGetSymbolAddress((void**)&kvb,  g_kv);
    cudaGetSymbolAddress((void**)&ksb,  g_ks);

    cudaFuncSetAttribute(mgemm<0>, cudaFuncAttributeMaxDynamicSharedMemorySize, GSMEM);
    cudaFuncSetAttribute(mgemm<1>, cudaFuncAttributeMaxDynamicSharedMemorySize, GSMEM);

    // bf16 hi/lo conversions
    split_x_kernel<<<(MTOT * KDIM / 4) / 256, 256>>>((const float4*)x, (uint2*)xhi, (uint2*)xlo);
    transpose_split_kernel<<<dim3(N_QKV / 32, KDIM / 32), dim3(32, 8)>>>(w_attn, wahi, walo, KDIM, N_QKV);
    transpose_split_kernel<<<dim3(N_PROJ / 32, KDIM / 32), dim3(32, 8)>>>(w_proj, wphi, wplo, KDIM, N_PROJ);

    // K1: qkv = x @ w_attn + b_attn (mma.sync), fused phi/mask epilogue
    mgemm<0><<<dim3(N_QKV / 128, MTOT / 128), 256, GSMEM>>>(xhi, xlo, wahi, walo,
                                                            b_attn, am, qkv, N_QKV);
    // K2: per-head kv state + ksum (split over 8 T-chunks, then reduce)
    kv_partial<<<BB * HH * 8, 256>>>(qkv, kvp, ksp);
    kv_reduce<<<BB * HH, 256>>>(kvp, ksp, kvb, ksb);
    // K3: normalized linear attention output -> y (bf16 hi/lo)
    y_kernel<<<dim3(TT / 128, BB * HH), 256>>>(qkv, kvb, ksb, yhi, ylo);
    // K4: out = y @ w_proj + b_proj (mma.sync)
    mgemm<1><<<dim3(N_PROJ / 128, MTOT / 128), 256, GSMEM>>>(yhi, ylo, wphi, wplo,
                                                             b_proj, nullptr, out, N_PROJ);
}

// round 7
// speedup vs baseline: 1.2753x; 1.2753x over previous
#include <cuda_runtime.h>
#include <cuda_fp16.h>
#include <math.h>
#include <stdint.h>

// Problem shape
#define BB 8
#define TT 2048
#define CC 1024
#define HH 16
#define DD 64
#define MTOT (BB*TT)      // 16384
#define KDIM 1024
#define N_QKV 3072
#define N_PROJ 1024

// ---------------- scratch (__device__ globals; no allocation allowed) -------
__device__ float  g_qkv [(size_t)MTOT * N_QKV];   // phi_q | phi_k*m | v*m
__device__ __half g_xhi [(size_t)MTOT * KDIM];
__device__ __half g_xlo [(size_t)MTOT * KDIM];
__device__ __half g_wahi[(size_t)N_QKV * KDIM];   // transposed [N,K], fp16 hi only
__device__ __half g_wphi[(size_t)N_PROJ * KDIM];
__device__ __half g_yhi [(size_t)MTOT * CC];
__device__ __half g_ylo [(size_t)MTOT * CC];
__device__ float g_kvp[8 * BB*HH * DD*DD];
__device__ float g_ksp[8 * BB*HH * DD];
__device__ float g_kv [BB*HH * DD*DD];
__device__ float g_ks [BB*HH * DD];

// ---------------- helpers ----------------------------------------------------
__device__ __forceinline__ uint32_t smem_u32(const void* p) {
    uint32_t a;
    asm("{ .reg .u64 t; cvta.to.shared.u64 t, %1; cvt.u32.u64 %0, t; }"
        : "=r"(a) : "l"(p));
    return a;
}
__device__ __forceinline__ void cpasync16(uint32_t dst, const void* src) {
    asm volatile("cp.async.cg.shared.global [%0], [%1], 16;" :: "r"(dst), "l"(src));
}
#define CP_COMMIT() asm volatile("cp.async.commit_group;" ::: "memory")
#define CP_WAIT2()  asm volatile("cp.async.wait_group 2;" ::: "memory")

__device__ __forceinline__ void ldsm4(uint32_t (&r)[4], uint32_t addr) {
    asm volatile("ldmatrix.sync.aligned.m8n8.x4.shared.b16 {%0,%1,%2,%3}, [%4];"
                 : "=r"(r[0]), "=r"(r[1]), "=r"(r[2]), "=r"(r[3]) : "r"(addr));
}
__device__ __forceinline__ void mma16816(float (&c)[4], const uint32_t (&a)[4],
                                         uint32_t b0, uint32_t b1) {
    asm volatile(
        "mma.sync.aligned.m16n8k16.row.col.f32.f16.f16.f32 "
        "{%0,%1,%2,%3}, {%4,%5,%6,%7}, {%8,%9}, {%0,%1,%2,%3};"
        : "+f"(c[0]), "+f"(c[1]), "+f"(c[2]), "+f"(c[3])
        : "r"(a[0]), "r"(a[1]), "r"(a[2]), "r"(a[3]), "r"(b0), "r"(b1));
}

__device__ __forceinline__ void split2h(float v, __half& h, __half& l) {
    h = __float2half(v);
    l = __float2half(v - __half2float(h));
}

// FFMA-only exp(x) (no MUFU), rel err ~2.4e-6.
__device__ __forceinline__ float fexp(float x) {
    x = fmaxf(x, -80.f);
    float t = x * 1.4426950408889634f;
    float r = t + 12582912.0f;
    int   n = __float_as_int(r) - 0x4B400000;
    float f = t - (r - 12582912.0f);
    float g = f * 0.6931471805599453f;
    float p = fmaf(g, 0.008333333f, 0.041666667f);
    p = fmaf(g, p, 0.166666667f);
    p = fmaf(g, p, 0.5f);
    p = fmaf(g, p, 1.0f);
    p = fmaf(g, p, 1.0f);
    return __int_as_float(__float_as_int(p) + (n << 23));
}

// XOR-swizzled smem offset: 64B rows of 4x16B chunks; chunk ^= (row>>1)&3.
__device__ __forceinline__ uint32_t swz(int row, int ch) {
    return (uint32_t)((row << 6) + (((ch ^ (row >> 1)) & 3) << 4));
}

// ---------------- conversion kernels ----------------------------------------
__global__ __launch_bounds__(256)
void split_x_kernel(const float4* __restrict__ in, uint2* __restrict__ hi,
                    uint2* __restrict__ lo) {
    size_t i = (size_t)blockIdx.x * blockDim.x + threadIdx.x;
    float4 v = in[i];
    __half h0, h1, h2, h3, l0, l1, l2, l3;
    split2h(v.x, h0, l0); split2h(v.y, h1, l1);
    split2h(v.z, h2, l2); split2h(v.w, h3, l3);
    uint32_t ha = (uint32_t)__half_as_ushort(h0) | ((uint32_t)__half_as_ushort(h1) << 16);
    uint32_t hb = (uint32_t)__half_as_ushort(h2) | ((uint32_t)__half_as_ushort(h3) << 16);
    uint32_t la = (uint32_t)__half_as_ushort(l0) | ((uint32_t)__half_as_ushort(l1) << 16);
    uint32_t lb = (uint32_t)__half_as_ushort(l2) | ((uint32_t)__half_as_ushort(l3) << 16);
    hi[i] = make_uint2(ha, hb);
    lo[i] = make_uint2(la, lb);
}

// w [K,N] row-major -> hi [N,K] (K-major), fp16
__global__ __launch_bounds__(256)
void transpose_h_kernel(const float* __restrict__ w, __half* __restrict__ hi,
                        int K, int N) {
    __shared__ float t[32][33];
    int n0 = blockIdx.x * 32, k0 = blockIdx.y * 32;
    int tx = threadIdx.x, ty = threadIdx.y;
#pragma unroll
    for (int i = 0; i < 4; i++)
        t[ty + i * 8][tx] = w[(size_t)(k0 + ty + i * 8) * N + n0 + tx];
    __syncthreads();
#pragma unroll
    for (int i = 0; i < 4; i++) {
        float v = t[tx][ty + i * 8];
        hi[(size_t)(n0 + ty + i * 8) * K + k0 + tx] = __float2half(v);
    }
}

// ---------------- mma.sync fp16 2-term GEMM ---------------------------------
// C[M,N] (fp32) = A[M,K] * B[N,K]^T + bias.
// A as fp16 hi+lo (2-term: (ah+al)*bh), B as fp16 hi only.
// Block: 128x128, BK=32, XOR-swizzled smem (24KB/stage), 4 buffers / depth-3
// prefetch, 8 warps (2x4), warp tile 64x32, 2 CTAs/SM.
#define BKG 32
#define OPB (128 * 64)          // 8192 B per operand tile
#define STGB (3 * OPB)          // 24576 B per stage (Ahi|Alo|Bhi)
#define NSTG 4
#define GSMEM (NSTG * STGB)     // 98304 B

template<int EPI>
__global__ __launch_bounds__(256, 2)
void mgemm(const __half* __restrict__ Ahi, const __half* __restrict__ Alo,
           const __half* __restrict__ Bhi,
           const float* __restrict__ bias, const int* __restrict__ am,
           float* __restrict__ Cout, int N)
{
    extern __shared__ char smem_raw[];
    const uint32_t sbase = smem_u32(smem_raw);
    const int tid = threadIdx.x;
    const int wid = tid >> 5, lane = tid & 31;
    const int warp_row = wid & 1;        // 0..1  (64 rows each)
    const int warp_col = wid >> 1;       // 0..3  (32 cols each)
    const int bm = blockIdx.y * 128;
    const int bn = blockIdx.x * 128;

    float acc[4][4][4];                  // [m-tile][n-tile][frag]
#pragma unroll
    for (int i = 0; i < 4; i++)
#pragma unroll
        for (int j = 0; j < 4; j++)
#pragma unroll
            for (int q = 0; q < 4; q++) acc[i][j][q] = 0.f;

    // stage loader: 128 rows x 4 chunks(16B) per operand; 2 rows/thread
    auto load_stage = [&](int s) {
        const int k0 = s * BKG;
        const uint32_t sb = sbase + (s % NSTG) * STGB;
#pragma unroll
        for (int i = 0; i < 2; i++) {
            int c = tid + i * 256;
            int row = c >> 2, ch = c & 3;
            uint32_t so = swz(row, ch);
            size_t ga = (size_t)(bm + row) * KDIM + k0 + ch * 8;
            size_t gb = (size_t)(bn + row) * KDIM + k0 + ch * 8;
            cpasync16(sb + 0 * OPB + so, Ahi + ga);
            cpasync16(sb + 1 * OPB + so, Alo + ga);
            cpasync16(sb + 2 * OPB + so, Bhi + gb);
        }
        CP_COMMIT();
    };

    const int NS = KDIM / BKG;   // 32
    load_stage(0); load_stage(1); load_stage(2);

    // per-lane ldmatrix fragment coordinates
    const int a_r = (lane & 7) + 8 * ((lane >> 3) & 1);   // row offset within 16
    const int a_k = 8 * (lane >> 4);                      // k offset 0/8
    const int b_r = (lane & 7) + 8 * (lane >> 4);         // n offset within 16
    const int b_k = 8 * ((lane >> 3) & 1);                // k offset 0/8

    for (int s = 0; s < NS; s++) {
        CP_WAIT2();
        __syncthreads();
        if (s + 3 < NS) load_stage(s + 3);

        const uint32_t sb = sbase + (s % NSTG) * STGB;

#pragma unroll
        for (int kk = 0; kk < 2; kk++) {
            uint32_t ah[4][4], al[4][4];
#pragma unroll
            for (int mi = 0; mi < 4; mi++) {
                int r = warp_row * 64 + mi * 16 + a_r;
                int ch = (kk * 16 + a_k) >> 3;
                uint32_t ro = swz(r, ch);
                ldsm4(ah[mi], sb + 0 * OPB + ro);
                ldsm4(al[mi], sb + 1 * OPB + ro);
            }
#pragma unroll
            for (int p = 0; p < 2; p++) {
                int rn = warp_col * 32 + p * 16 + b_r;
                int chb = (kk * 16 + b_k) >> 3;
                uint32_t bo = swz(rn, chb);
                uint32_t bh[4];
                ldsm4(bh, sb + 2 * OPB + bo);
                // term-major: 8 independent MMAs per term
#pragma unroll
                for (int mi = 0; mi < 4; mi++)
#pragma unroll
                    for (int j = 0; j < 2; j++)
                        mma16816(acc[mi][2 * p + j], ah[mi], bh[2 * j], bh[2 * j + 1]);
#pragma unroll
                for (int mi = 0; mi < 4; mi++)
#pragma unroll
                    for (int j = 0; j < 2; j++)
                        mma16816(acc[mi][2 * p + j], al[mi], bh[2 * j], bh[2 * j + 1]);
            }
        }
    }

    // ---------------- epilogue ----------------
    const int er = lane >> 2;            // 0..7
    const int ec = (lane & 3) * 2;       // 0,2,4,6
#pragma unroll
    for (int mi = 0; mi < 4; mi++) {
#pragma unroll
        for (int half = 0; half < 2; half++) {
            int row = bm + warp_row * 64 + mi * 16 + er + half * 8;
            float mv = 1.f;
            if (EPI == 0) mv = (am[row] > 0) ? 1.f : 0.f;
#pragma unroll
            for (int ni = 0; ni < 4; ni++) {
                int col = bn + warp_col * 32 + ni * 8 + ec;
                float v0 = acc[mi][ni][2 * half]     + bias[col];
                float v1 = acc[mi][ni][2 * half + 1] + bias[col + 1];
                if (EPI == 0) {
                    if (col < 2048) {
                        v0 = (v0 > 0.f) ? (v0 + 1.f) : fexp(v0);   // elu + 1
                        v1 = (v1 > 0.f) ? (v1 + 1.f) : fexp(v1);
                    }
                    if (col >= 1024) { v0 *= mv; v1 *= mv; }
                }
                *(float2*)(Cout + (size_t)row * N + col) = make_float2(v0, v1);
            }
        }
    }
}

// ---------------- K2: per (b,h,chunk) partial kv / ksum ---------------------
__global__ __launch_bounds__(256)
void kv_partial(const float* __restrict__ qkv, float* __restrict__ kvp,
                float* __restrict__ ksp)
{
    __shared__ float ks[16][64];
    __shared__ float vs[16][64];

    const int bh = blockIdx.x >> 3;
    const int chn = blockIdx.x & 7;
    const int b = bh >> 4, h = bh & 15;
    const int tid = threadIdx.x;

    const float* kb = qkv + (size_t)b * TT * N_QKV + 1024 + h * DD;
    const float* vb = kb + 1024;

    const int lr  = tid >> 4;
    const int lc4 = (tid & 15) * 4;
    const int i0  = (tid >> 4) * 4;
    const int j0  = (tid & 15) * 4;

    float acc[4][4];
#pragma unroll
    for (int i = 0; i < 4; i++)
#pragma unroll
        for (int j = 0; j < 4; j++) acc[i][j] = 0.f;
    float ksum4[4] = {0.f, 0.f, 0.f, 0.f};
    const bool owns_ksum = ((tid & 15) == 0);

    const int tbeg = chn * (TT / 8);
    for (int t0 = tbeg; t0 < tbeg + TT / 8; t0 += 16) {
        size_t off = (size_t)(t0 + lr) * N_QKV + lc4;
        *(float4*)&ks[lr][lc4] = *(const float4*)(kb + off);
        *(float4*)&vs[lr][lc4] = *(const float4*)(vb + off);
        __syncthreads();
#pragma unroll
        for (int t = 0; t < 16; t++) {
            float4 k4 = *(float4*)&ks[t][i0];
            float4 v4 = *(float4*)&vs[t][j0];
            float ka[4] = {k4.x, k4.y, k4.z, k4.w};
            float va[4] = {v4.x, v4.y, v4.z, v4.w};
#pragma unroll
            for (int i = 0; i < 4; i++)
#pragma unroll
                for (int j = 0; j < 4; j++)
                    acc[i][j] = fmaf(ka[i], va[j], acc[i][j]);
            if (owns_ksum) {
#pragma unroll
                for (int i = 0; i < 4; i++) ksum4[i] += ka[i];
            }
        }
        __syncthreads();
    }

    float* kvdst = kvp + ((size_t)chn * 128 + bh) * DD * DD;
#pragma unroll
    for (int i = 0; i < 4; i++)
        *(float4*)&kvdst[(i0 + i) * DD + j0] =
            make_float4(acc[i][0], acc[i][1], acc[i][2], acc[i][3]);
    if (owns_ksum) {
#pragma unroll
        for (int i = 0; i < 4; i++)
            ksp[((size_t)chn * 128 + bh) * DD + i0 + i] = ksum4[i];
    }
}

__global__ __launch_bounds__(256)
void kv_reduce(const float* __restrict__ kvp, const float* __restrict__ ksp,
               float* __restrict__ kv, float* __restrict__ ks)
{
    const int bh = blockIdx.x;
    const int tid = threadIdx.x;
    for (int i = tid; i < DD * DD; i += 256) {
        float s = 0.f;
#pragma unroll
        for (int c = 0; c < 8; c++) s += kvp[((size_t)c * 128 + bh) * DD * DD + i];
        kv[(size_t)bh * DD * DD + i] = s;
    }
    if (tid < DD) {
        float s = 0.f;
#pragma unroll
        for (int c = 0; c < 8; c++) s += ksp[((size_t)c * 128 + bh) * DD + tid];
        ks[(size_t)bh * DD + tid] = s;
    }
}

// ---------------- K3: y = (phi_q . kv) / max(phi_q . ksum, eps) -> fp16 hi/lo
__global__ __launch_bounds__(256)
void y_kernel(const float* __restrict__ qkv, const float* __restrict__ kv,
              const float* __restrict__ ksum, __half* __restrict__ yhi,
              __half* __restrict__ ylo)
{
    __shared__ float kvs[DD * DD];
    __shared__ float kss[DD];

    const int bh = blockIdx.y;
    const int b = bh >> 4, h = bh & 15;
    const int tid = threadIdx.x;

    const float4* kvsrc = (const float4*)(kv + (size_t)bh * DD * DD);
#pragma unroll
    for (int i = 0; i < 4; i++)
        ((float4*)kvs)[tid + i * 256] = kvsrc[tid + i * 256];
    if (tid < DD) kss[tid] = ksum[bh * DD + tid];
    __syncthreads();

    const int t = blockIdx.x * 128 + (tid >> 1);
    const int f0 = (tid & 1) * 32;
    const float* qrow = qkv + (size_t)(b * TT + t) * N_QKV + h * DD;

    float acc[32];
#pragma unroll
    for (int f = 0; f < 32; f++) acc[f] = 0.f;
    float den = 0.f;

#pragma unroll 4
    for (int d4 = 0; d4 < 16; d4++) {
        float4 q4 = *(const float4*)(qrow + d4 * 4);
        float qa[4] = {q4.x, q4.y, q4.z, q4.w};
#pragma unroll
        for (int u = 0; u < 4; u++) {
            int d = d4 * 4 + u;
            den = fmaf(qa[u], kss[d], den);
            const float* kr = &kvs[d * DD + f0];
#pragma unroll
            for (int f = 0; f < 32; f += 4) {
                float4 kv4 = *(const float4*)(kr + f);
                acc[f]     = fmaf(qa[u], kv4.x, acc[f]);
                acc[f + 1] = fmaf(qa[u], kv4.y, acc[f + 1]);
                acc[f + 2] = fmaf(qa[u], kv4.z, acc[f + 2]);
                acc[f + 3] = fmaf(qa[u], kv4.w, acc[f + 3]);
            }
        }
    }

    const float inv = 1.f / fmaxf(den, 1e-8f);
    const size_t off = (size_t)(b * TT + t) * CC + h * DD + f0;
#pragma unroll
    for (int f = 0; f < 32; f += 8) {
        uint32_t wh[4], wl[4];
#pragma unroll
        for (int j = 0; j < 4; j++) {
            float v0 = acc[f + 2 * j]     * inv;
            float v1 = acc[f + 2 * j + 1] * inv;
            __half h0, l0, h1, l1;
            split2h(v0, h0, l0);
            split2h(v1, h1, l1);
            wh[j] = (uint32_t)__half_as_ushort(h0) | ((uint32_t)__half_as_ushort(h1) << 16);
            wl[j] = (uint32_t)__half_as_ushort(l0) | ((uint32_t)__half_as_ushort(l1) << 16);
        }
        *(uint4*)(yhi + off + f) = make_uint4(wh[0], wh[1], wh[2], wh[3]);
        *(uint4*)(ylo + off + f) = make_uint4(wl[0], wl[1], wl[2], wl[3]);
    }
}

// ---------------------------------------------------------------------------
extern "C" void kernel_launch(void* const* d_in, const int* in_sizes, int n_in,
                              void* d_out, int out_size)
{
    const float* x      = (const float*)d_in[0];
    const int*   am     = (const int*)  d_in[1];
    const float* w_attn = (const float*)d_in[2];
    const float* b_attn = (const float*)d_in[3];
    const float* w_proj = (const float*)d_in[4];
    const float* b_proj = (const float*)d_in[5];
    float* out = (float*)d_out;

    float *qkv, *kvp, *ksp, *kvb, *ksb;
    __half *xhi, *xlo, *wahi, *wphi, *yhi, *ylo;
    cudaGetSymbolAddress((void**)&qkv,  g_qkv);
    cudaGetSymbolAddress((void**)&xhi,  g_xhi);
    cudaGetSymbolAddress((void**)&xlo,  g_xlo);
    cudaGetSymbolAddress((void**)&wahi, g_wahi);
    cudaGetSymbolAddress((void**)&wphi, g_wphi);
    cudaGetSymbolAddress((void**)&yhi,  g_yhi);
    cudaGetSymbolAddress((void**)&ylo,  g_ylo);
    cudaGetSymbolAddress((void**)&kvp,  g_kvp);
    cudaGetSymbolAddress((void**)&ksp,  g_ksp);
    cudaGetSymbolAddress((void**)&kvb,  g_kv);
    cudaGetSymbolAddress((void**)&ksb,  g_ks);

    cudaFuncSetAttribute(mgemm<0>, cudaFuncAttributeMaxDynamicSharedMemorySize, GSMEM);
    cudaFuncSetAttribute(mgemm<1>, cudaFuncAttributeMaxDynamicSharedMemorySize, GSMEM);

    // fp16 conversions
    split_x_kernel<<<(MTOT * KDIM / 4) / 256, 256>>>((const float4*)x, (uint2*)xhi, (uint2*)xlo);
    transpose_h_kernel<<<dim3(N_QKV / 32, KDIM / 32), dim3(32, 8)>>>(w_attn, wahi, KDIM, N_QKV);
    transpose_h_kernel<<<dim3(N_PROJ / 32, KDIM / 32), dim3(32, 8)>>>(w_proj, wphi, KDIM, N_PROJ);

    // K1: qkv = x @ w_attn + b_attn (mma.sync fp16 2-term), fused phi/mask
    mgemm<0><<<dim3(N_QKV / 128, MTOT / 128), 256, GSMEM>>>(xhi, xlo, wahi,
                                                            b_attn, am, qkv, N_QKV);
    // K2: per-head kv state + ksum (split over 8 T-chunks, then reduce)
    kv_partial<<<BB * HH * 8, 256>>>(qkv, kvp, ksp);
    kv_reduce<<<BB * HH, 256>>>(kvp, ksp, kvb, ksb);
    // K3: normalized linear attention output -> y (fp16 hi/lo)
    y_kernel<<<dim3(TT / 128, BB * HH), 256>>>(qkv, kvb, ksb, yhi, ylo);
    // K4: out = y @ w_proj + b_proj (mma.sync fp16 2-term)
    mgemm<1><<<dim3(N_PROJ / 128, MTOT / 128), 256, GSMEM>>>(yhi, ylo, wphi,
                                                             b_proj, nullptr, out, N_PROJ);
}